// round 1
// baseline (speedup 1.0000x reference)
#include <cuda_runtime.h>
#include <math.h>

#define Bk   64
#define Tk   512
#define Dd   96
#define TYk  512
#define Hk   4
#define DKk  32
#define Ek   128
#define Pk   2
#define Lk   64
#define HIDk 128

// Scratch (no allocation allowed) -------------------------------------------
__device__ float g_v[8 * 128];        // folded (q·k_w) per (h,p)
__device__ float g_c[8];              // q·k_b per (h,p)
__device__ float g_constL[64];        // ob + ones-half contribution of ow
__device__ float g_coeffs[64 * 2 * 64];

// ---------------------------------------------------------------------------
// Kernel 0: tiny precompute (1 block).
//   q_proj = query @ q_w + q_b              [P,E]
//   g_v[hp][e'] = sum_d q_proj[p][h*32+d] * k_w[e'][h*32+d]
//   g_c[hp]     = sum_d q_proj[p][h*32+d] * k_b[h*32+d]
//   g_constL[l] = ob[l] + sum over "ones" rows of ow
// ---------------------------------------------------------------------------
__global__ __launch_bounds__(256) void precompute_kernel(
    const float* __restrict__ query, const float* __restrict__ q_w,
    const float* __restrict__ q_b,   const float* __restrict__ k_w,
    const float* __restrict__ k_b,   const float* __restrict__ ow,
    const float* __restrict__ ob)
{
    __shared__ float s_query[2 * 128];
    __shared__ float s_qp[2 * 128];
    int tid = threadIdx.x;
    s_query[tid] = query[tid];
    __syncthreads();
    {
        int p = tid >> 7, e = tid & 127;
        float acc = q_b[e];
        #pragma unroll 8
        for (int i = 0; i < 128; ++i)
            acc = fmaf(s_query[p * 128 + i], q_w[i * 128 + e], acc);
        s_qp[tid] = acc;
    }
    __syncthreads();
    for (int idx = tid; idx < 8 * 128; idx += 256) {
        int hp = idx >> 7, ein = idx & 127;
        int h = hp >> 1, p = hp & 1;
        float acc = 0.f;
        #pragma unroll 8
        for (int d = 0; d < 32; ++d)
            acc = fmaf(s_qp[p * 128 + h * 32 + d], k_w[ein * 128 + h * 32 + d], acc);
        g_v[idx] = acc;
    }
    if (tid < 8) {
        int h = tid >> 1, p = tid & 1;
        float acc = 0.f;
        for (int d = 0; d < 32; ++d)
            acc = fmaf(s_qp[p * 128 + h * 32 + d], k_b[h * 32 + d], acc);
        g_c[tid] = acc;
    }
    if (tid >= 64 && tid < 128) {
        int l = tid - 64;
        float acc = ob[l];
        for (int h = 0; h < 4; ++h)
            for (int j = 0; j < 96; ++j)
                acc += ow[(h * 192 + 96 + j) * 64 + l];
        g_constL[l] = acc;
    }
}

// ---------------------------------------------------------------------------
// Kernel 1: per-batch attention. One block per b, 768 threads.
//   A: scores[hp][t] from scalar timestep via folded v
//   B: per-hp max + exp
//   C: masked weighted sums num/den over t (smem-tiled X,M)
//   D: coeffs[b][p][l] projection through active half of ow
// ---------------------------------------------------------------------------
__global__ __launch_bounds__(768) void attn_kernel(
    const float* __restrict__ timesteps, const float* __restrict__ X,
    const float* __restrict__ Mm,        const float* __restrict__ te_w,
    const float* __restrict__ te_b,      const float* __restrict__ ow)
{
    __shared__ float s_v[8][128];
    __shared__ float s_e[8][512];
    __shared__ float s_X[32 * 96];
    __shared__ float s_M[32 * 96];
    __shared__ float s_xa[8 * 96];
    __shared__ float s_max[8];

    int b = blockIdx.x;
    int tid = threadIdx.x;
    for (int i = tid; i < 8 * 128; i += 768) ((float*)s_v)[i] = g_v[i];
    __syncthreads();

    // ---- Phase A: scores ----
    if (tid < 512) {
        float ts = timesteps[b * Tk + tid];
        float acc[8];
        #pragma unroll
        for (int hp = 0; hp < 8; ++hp) acc[hp] = g_c[hp];
        const float4* w4p = (const float4*)te_w;
        const float4* b4p = (const float4*)te_b;
        #pragma unroll 8
        for (int e4 = 0; e4 < 32; ++e4) {
            float4 w4 = __ldg(&w4p[e4]);
            float4 b4 = __ldg(&b4p[e4]);
            float4 em;
            em.x = sinf(fmaf(ts, w4.x, b4.x));   // (e % 4 == 0) -> sin
            em.y = fmaf(ts, w4.y, b4.y);
            em.z = fmaf(ts, w4.z, b4.z);
            em.w = fmaf(ts, w4.w, b4.w);
            #pragma unroll
            for (int hp = 0; hp < 8; ++hp) {
                float4 v4 = *(const float4*)&s_v[hp][e4 * 4];
                acc[hp] += em.x * v4.x + em.y * v4.y + em.z * v4.z + em.w * v4.w;
            }
        }
        const float scale = 0.17677669529663687f;  // 1/sqrt(32)
        #pragma unroll
        for (int hp = 0; hp < 8; ++hp) s_e[hp][tid] = acc[hp] * scale;
    }
    __syncthreads();

    // ---- Phase B: max + exp ----
    int warp = tid >> 5, lane = tid & 31;
    if (warp < 8) {
        float m = -1e30f;
        for (int t = lane; t < 512; t += 32) m = fmaxf(m, s_e[warp][t]);
        #pragma unroll
        for (int o = 16; o; o >>= 1) m = fmaxf(m, __shfl_xor_sync(0xffffffffu, m, o));
        if (lane == 0) s_max[warp] = m;
    }
    __syncthreads();
    for (int idx = tid; idx < 8 * 512; idx += 768) {
        int hp = idx >> 9, t = idx & 511;
        s_e[hp][t] = __expf(s_e[hp][t] - s_max[hp]);
    }
    __syncthreads();

    // ---- Phase C: masked weighted accumulation ----
    {
        int hp = tid / 96, f = tid - hp * 96;   // 768 = 8*96, all threads valid
        float num = 0.f, den = 0.f;
        const float* Xb = X + (size_t)b * Tk * Dd;
        const float* Mb = Mm + (size_t)b * Tk * Dd;
        for (int c = 0; c < 16; ++c) {
            for (int i = tid; i < 32 * 96; i += 768) {
                s_X[i] = Xb[c * 32 * 96 + i];
                s_M[i] = Mb[c * 32 * 96 + i];
            }
            __syncthreads();
            #pragma unroll 8
            for (int tt = 0; tt < 32; ++tt) {
                float e = s_e[hp][c * 32 + tt];
                float m = s_M[tt * 96 + f];
                float x = s_X[tt * 96 + f];
                den = fmaf(e, m, den);
                num = fmaf(e, m * x, num);
            }
            __syncthreads();
        }
        s_xa[hp * 96 + f] = num / den;
    }
    __syncthreads();

    // ---- Phase D: coeffs (128 outputs x 6 row-segments) ----
    {
        int outIdx = tid & 127;   // p*64 + l
        int seg = tid >> 7;       // 0..5, rows seg*64 .. seg*64+63 of 384 active rows
        int p = outIdx >> 6, l = outIdx & 63;
        float acc = 0.f;
        #pragma unroll 4
        for (int r = seg * 64; r < seg * 64 + 64; ++r) {
            int h = r / 96, f = r - h * 96;
            acc = fmaf(s_xa[(h * 2 + p) * 96 + f], ow[(h * 192 + f) * 64 + l], acc);
        }
        ((float*)s_e)[tid] = acc;   // s_e free now, reuse for reduction
    }
    __syncthreads();
    if (tid < 128) {
        int p = tid >> 6, l = tid & 63;
        float acc = g_constL[l];
        #pragma unroll
        for (int seg = 0; seg < 6; ++seg) acc += ((float*)s_e)[seg * 128 + tid];
        g_coeffs[b * 128 + p * 64 + l] = acc;
    }
}

// ---------------------------------------------------------------------------
// Kernel 2: decoder. Block = (tile of 64 ty, b). 256 threads.
//   h1[ty][i] = relu(A[i] + y[ty]*B[i]),  out = h1 @ w2 + b2
//   4x6 register blocking over (ty, j), i-dim chunked through smem.
// ---------------------------------------------------------------------------
__global__ __launch_bounds__(256) void decoder_kernel(
    const float* __restrict__ y_ts, const float* __restrict__ w1,
    const float* __restrict__ b1,   const float* __restrict__ w2,
    const float* __restrict__ b2,   float* __restrict__ out)
{
    __shared__ float sA[128], sB[128], sy[64], sc0[64], sc1[64];
    __shared__ float sw2[64 * 96];
    __shared__ float sh1[64][65];   // padded: avoid 8-way bank conflicts

    int b = blockIdx.y, tile = blockIdx.x;
    int tid = threadIdx.x;

    if (tid < 64) {
        sc0[tid] = g_coeffs[b * 128 + tid];
        sc1[tid] = g_coeffs[b * 128 + 64 + tid];
    } else if (tid < 128) {
        sy[tid - 64] = y_ts[b * TYk + tile * 64 + (tid - 64)];
    }
    __syncthreads();
    if (tid < 128) {
        float a = b1[tid], bb = 0.f;
        #pragma unroll 8
        for (int l = 0; l < 64; ++l) {
            float w = w1[l * 128 + tid];
            a = fmaf(sc0[l], w, a);
            bb = fmaf(sc1[l], w, bb);
        }
        sA[tid] = a; sB[tid] = bb;
    }
    __syncthreads();

    int tg = tid >> 4, jg = tid & 15;
    int ty0 = tg * 4, j0 = jg * 6;
    float acc[4][6];
    #pragma unroll
    for (int r = 0; r < 4; ++r)
        #pragma unroll
        for (int u = 0; u < 6; ++u) acc[r][u] = 0.f;

    for (int c = 0; c < 2; ++c) {
        for (int i = tid; i < 64 * 96; i += 256) sw2[i] = w2[c * 64 * 96 + i];
        for (int i = tid; i < 64 * 64; i += 256) {
            int ty = i >> 6, ic = i & 63;
            sh1[ty][ic] = fmaxf(fmaf(sy[ty], sB[c * 64 + ic], sA[c * 64 + ic]), 0.f);
        }
        __syncthreads();
        #pragma unroll 4
        for (int ic = 0; ic < 64; ++ic) {
            float h0 = sh1[ty0][ic], h1v = sh1[ty0 + 1][ic];
            float h2 = sh1[ty0 + 2][ic], h3 = sh1[ty0 + 3][ic];
            #pragma unroll
            for (int u = 0; u < 6; ++u) {
                float w = sw2[ic * 96 + j0 + u];
                acc[0][u] = fmaf(h0, w, acc[0][u]);
                acc[1][u] = fmaf(h1v, w, acc[1][u]);
                acc[2][u] = fmaf(h2, w, acc[2][u]);
                acc[3][u] = fmaf(h3, w, acc[3][u]);
            }
        }
        __syncthreads();
    }
    #pragma unroll
    for (int r = 0; r < 4; ++r) {
        int ty = tile * 64 + ty0 + r;
        float* o = out + ((size_t)b * TYk + ty) * Dd + j0;
        #pragma unroll
        for (int u = 0; u < 6; ++u) o[u] = acc[r][u] + b2[j0 + u];
    }
}

// ---------------------------------------------------------------------------
extern "C" void kernel_launch(void* const* d_in, const int* in_sizes, int n_in,
                              void* d_out, int out_size)
{
    const float* timesteps = (const float*)d_in[0];
    const float* X         = (const float*)d_in[1];
    const float* Mm        = (const float*)d_in[2];
    const float* y_ts      = (const float*)d_in[3];
    const float* te_w      = (const float*)d_in[4];
    const float* te_b      = (const float*)d_in[5];
    const float* query     = (const float*)d_in[6];
    const float* q_w       = (const float*)d_in[7];
    const float* q_b       = (const float*)d_in[8];
    const float* k_w       = (const float*)d_in[9];
    const float* k_b       = (const float*)d_in[10];
    const float* ow        = (const float*)d_in[11];
    const float* ob        = (const float*)d_in[12];
    const float* w1        = (const float*)d_in[13];
    const float* b1        = (const float*)d_in[14];
    const float* w2        = (const float*)d_in[15];
    const float* b2        = (const float*)d_in[16];
    float* out = (float*)d_out;

    precompute_kernel<<<1, 256>>>(query, q_w, q_b, k_w, k_b, ow, ob);
    attn_kernel<<<64, 768>>>(timesteps, X, Mm, te_w, te_b, ow);
    decoder_kernel<<<dim3(8, 64), 256>>>(y_ts, w1, b1, w2, b2, out);
}

// round 2
// speedup vs baseline: 2.2743x; 2.2743x over previous
#include <cuda_runtime.h>
#include <math.h>

#define Bk   64
#define Tk   512
#define Dd   96
#define TYk  512
#define Ek   128
#define Pk   2
#define Lk   64
#define HIDk 128

typedef unsigned long long u64;

// ---------------- f32x2 packed math helpers (sm_103a) ----------------------
__device__ __forceinline__ u64 ffma2(u64 a, u64 b, u64 c) {
    u64 d;
    asm("fma.rn.f32x2 %0, %1, %2, %3;" : "=l"(d) : "l"(a), "l"(b), "l"(c));
    return d;
}
__device__ __forceinline__ u64 pack2(float lo, float hi) {
    u64 d; asm("mov.b64 %0, {%1, %2};" : "=l"(d) : "f"(lo), "f"(hi)); return d;
}
__device__ __forceinline__ float2 unpack2(u64 v) {
    float2 r; asm("mov.b64 {%0, %1}, %2;" : "=f"(r.x), "=f"(r.y) : "l"(v)); return r;
}

// Scratch (no allocation allowed) -------------------------------------------
__device__ float g_v[8 * 128];        // folded (q·k_w) per (h,p):  hp = h*2+p
__device__ float g_c[8];              // q·k_b per (h,p)
__device__ float g_constL[64];        // ob + ones-half contribution of ow
__device__ float g_coeffs[64 * 2 * 64];

// ---------------------------------------------------------------------------
// Kernel 0: precompute, grid=2 x 512 threads.
//   block 0: q_proj = query@q_w + q_b; g_v[hp][e'] = qp . k_w row; g_c
//   block 1: g_constL[l] = ob[l] + sum of "ones" rows of ow (coalesced)
// ---------------------------------------------------------------------------
__global__ __launch_bounds__(512) void precompute_kernel(
    const float* __restrict__ query, const float* __restrict__ q_w,
    const float* __restrict__ q_b,   const float* __restrict__ k_w,
    const float* __restrict__ k_b,   const float* __restrict__ ow,
    const float* __restrict__ ob)
{
    int tid = threadIdx.x;
    if (blockIdx.x == 0) {
        __shared__ float s_q[256];
        __shared__ float s_qp[256];
        __shared__ float s_kw[64][129];
        if (tid < 256) s_q[tid] = query[tid];
        __syncthreads();
        if (tid < 256) {
            int p = tid >> 7, e = tid & 127;
            float acc = q_b[e];
            #pragma unroll 8
            for (int i = 0; i < 128; ++i)
                acc = fmaf(s_q[p * 128 + i], q_w[i * 128 + e], acc);
            s_qp[tid] = acc;
        }
        __syncthreads();
        for (int half = 0; half < 2; ++half) {
            for (int i = tid; i < 64 * 128; i += 512) {
                int r = i >> 7, c = i & 127;
                s_kw[r][c] = k_w[(half * 64 + r) * 128 + c];
            }
            __syncthreads();
            {
                int hp = tid >> 6, eloc = tid & 63;
                int h = hp >> 1, p = hp & 1;
                float acc = 0.f;
                #pragma unroll 8
                for (int d = 0; d < 32; ++d)
                    acc = fmaf(s_qp[p * 128 + h * 32 + d], s_kw[eloc][h * 32 + d], acc);
                g_v[hp * 128 + half * 64 + eloc] = acc;
            }
            __syncthreads();
        }
        if (tid < 8) {
            int h = tid >> 1, p = tid & 1;
            float acc = 0.f;
            #pragma unroll
            for (int d = 0; d < 32; ++d)
                acc = fmaf(s_qp[p * 128 + h * 32 + d], k_b[h * 32 + d], acc);
            g_c[tid] = acc;
        }
    } else {
        __shared__ float s_red[512];
        int rg = tid >> 6, l = tid & 63;
        float a = 0.f;
        for (int r = rg; r < 384; r += 8) {
            int h = r / 96, j = r - h * 96;
            a += ow[(h * 192 + 96 + j) * 64 + l];
        }
        s_red[rg * 64 + l] = a;
        __syncthreads();
        if (tid < 64) {
            float acc = ob[tid];
            #pragma unroll
            for (int g = 0; g < 8; ++g) acc += s_red[g * 64 + tid];
            g_constL[tid] = acc;
        }
    }
}

// ---------------------------------------------------------------------------
// Kernel 1: per-batch attention. One block per b, 768 threads.
// ---------------------------------------------------------------------------
__global__ __launch_bounds__(768) void attn_kernel(
    const float* __restrict__ timesteps, const float* __restrict__ X,
    const float* __restrict__ Mm,        const float* __restrict__ te_w,
    const float* __restrict__ te_b,      const float* __restrict__ ow)
{
    __shared__ __align__(16) float s_vt[128][8];   // transposed g_v: [e][hp]
    __shared__ __align__(16) float s_et[512][8];   // scores->exp, [t][hp]
    __shared__ __align__(16) float s_XM[6144];     // X chunk | M chunk; reused as partials
    __shared__ float s_xa[8 * 96];
    __shared__ float s_max[8];
    __shared__ float s_c[8];

    int b = blockIdx.x;
    int tid = threadIdx.x;

    for (int i = tid; i < 1024; i += 768)
        s_vt[i >> 3][i & 7] = g_v[(i & 7) * 128 + (i >> 3)];
    if (tid < 8) s_c[tid] = g_c[tid];
    __syncthreads();

    // ---- Phase A: scores (transposed store) ----
    if (tid < 512) {
        float ts = timesteps[b * Tk + tid];
        u64 acc2[4];
        #pragma unroll
        for (int q = 0; q < 4; ++q) acc2[q] = pack2(s_c[2 * q], s_c[2 * q + 1]);
        const float4* w4p = (const float4*)te_w;
        const float4* b4p = (const float4*)te_b;
        #pragma unroll 4
        for (int e4 = 0; e4 < 32; ++e4) {
            float4 w4 = __ldg(&w4p[e4]);
            float4 b4 = __ldg(&b4p[e4]);
            float em[4];
            em[0] = __sinf(fmaf(ts, w4.x, b4.x));   // (e % 4 == 0) -> sin
            em[1] = fmaf(ts, w4.y, b4.y);
            em[2] = fmaf(ts, w4.z, b4.z);
            em[3] = fmaf(ts, w4.w, b4.w);
            #pragma unroll
            for (int j = 0; j < 4; ++j) {
                u64 emd = pack2(em[j], em[j]);
                const ulonglong2* vp = (const ulonglong2*)&s_vt[e4 * 4 + j][0];
                ulonglong2 va = vp[0];
                acc2[0] = ffma2(emd, va.x, acc2[0]);
                acc2[1] = ffma2(emd, va.y, acc2[1]);
                ulonglong2 vb = *(const ulonglong2*)&s_vt[e4 * 4 + j][4];
                acc2[2] = ffma2(emd, vb.x, acc2[2]);
                acc2[3] = ffma2(emd, vb.y, acc2[3]);
            }
        }
        const float scale = 0.17677669529663687f;  // 1/sqrt(32)
        float2 a0 = unpack2(acc2[0]), a1 = unpack2(acc2[1]);
        float2 a2 = unpack2(acc2[2]), a3 = unpack2(acc2[3]);
        float4 f0 = make_float4(a0.x * scale, a0.y * scale, a1.x * scale, a1.y * scale);
        float4 f1 = make_float4(a2.x * scale, a2.y * scale, a3.x * scale, a3.y * scale);
        *(float4*)&s_et[tid][0] = f0;
        *(float4*)&s_et[tid][4] = f1;
    }
    __syncthreads();

    // ---- Phase B: per-hp max, then exp in place ----
    int warp = tid >> 5, lane = tid & 31;
    if (warp < 8) {
        float m = -1e30f;
        for (int t = lane; t < 512; t += 32) m = fmaxf(m, s_et[t][warp]);
        #pragma unroll
        for (int o = 16; o; o >>= 1) m = fmaxf(m, __shfl_xor_sync(0xffffffffu, m, o));
        if (lane == 0) s_max[warp] = m;
    }
    __syncthreads();
    for (int idx = tid; idx < 8 * 512; idx += 768) {
        int t = idx >> 3, hp = idx & 7;
        s_et[t][hp] = __expf(s_et[t][hp] - s_max[hp]);
    }
    __syncthreads();

    // ---- Phase C: masked weighted accumulation, register-blocked over hp ----
    int tsub = tid / 96, f = tid - tsub * 96;    // 768 = 8 * 96; warp-uniform tsub
    u64 num2[4], den2[4];
    #pragma unroll
    for (int q = 0; q < 4; ++q) { num2[q] = 0ull; den2[q] = 0ull; }
    {
        const float* Xb = X + (size_t)b * Tk * Dd;
        const float* Mb = Mm + (size_t)b * Tk * Dd;
        for (int c = 0; c < 16; ++c) {
            #pragma unroll
            for (int i = tid; i < 3072; i += 768) {
                s_XM[i]        = Xb[c * 3072 + i];
                s_XM[3072 + i] = Mb[c * 3072 + i];
            }
            __syncthreads();
            #pragma unroll
            for (int q = 0; q < 4; ++q) {
                int tl = tsub * 4 + q;           // 0..31 within chunk
                float x = s_XM[tl * 96 + f];
                float m = s_XM[3072 + tl * 96 + f];
                int t = c * 32 + tl;
                ulonglong2 e01 = *(const ulonglong2*)&s_et[t][0];
                ulonglong2 e23 = *(const ulonglong2*)&s_et[t][4];
                float xm = x * m;
                u64 md  = pack2(m, m);
                u64 xmd = pack2(xm, xm);
                den2[0] = ffma2(e01.x, md, den2[0]);
                den2[1] = ffma2(e01.y, md, den2[1]);
                den2[2] = ffma2(e23.x, md, den2[2]);
                den2[3] = ffma2(e23.y, md, den2[3]);
                num2[0] = ffma2(e01.x, xmd, num2[0]);
                num2[1] = ffma2(e01.y, xmd, num2[1]);
                num2[2] = ffma2(e23.x, xmd, num2[2]);
                num2[3] = ffma2(e23.y, xmd, num2[3]);
            }
            __syncthreads();
        }
    }
    // reduce partials across tsub; s_XM (6144 floats = 8*8*96) reused
    int hpr = tid / 96, fr = tid - hpr * 96;
    float r_num, r_den;
    {
        #pragma unroll
        for (int q = 0; q < 4; ++q) {
            float2 n = unpack2(num2[q]);
            s_XM[tsub * 768 + (2 * q) * 96 + f]     = n.x;
            s_XM[tsub * 768 + (2 * q + 1) * 96 + f] = n.y;
        }
        __syncthreads();
        r_num = 0.f;
        #pragma unroll
        for (int g = 0; g < 8; ++g) r_num += s_XM[g * 768 + hpr * 96 + fr];
        __syncthreads();
        #pragma unroll
        for (int q = 0; q < 4; ++q) {
            float2 d = unpack2(den2[q]);
            s_XM[tsub * 768 + (2 * q) * 96 + f]     = d.x;
            s_XM[tsub * 768 + (2 * q + 1) * 96 + f] = d.y;
        }
        __syncthreads();
        r_den = 0.f;
        #pragma unroll
        for (int g = 0; g < 8; ++g) r_den += s_XM[g * 768 + hpr * 96 + fr];
        s_xa[hpr * 96 + fr] = r_num / r_den;
    }
    __syncthreads();

    // ---- Phase D: coeffs (128 outputs x 6 row-segments) ----
    float* s_scr = (float*)s_et;
    {
        int outIdx = tid & 127;   // p*64 + l
        int seg = tid >> 7;       // 0..5
        int p = outIdx >> 6, l = outIdx & 63;
        float acc = 0.f;
        #pragma unroll 4
        for (int r = seg * 64; r < seg * 64 + 64; ++r) {
            int h = r / 96, ff = r - h * 96;
            acc = fmaf(s_xa[(h * 2 + p) * 96 + ff], ow[(h * 192 + ff) * 64 + l], acc);
        }
        s_scr[tid] = acc;
    }
    __syncthreads();
    if (tid < 128) {
        int l = tid & 63;
        float acc = g_constL[l];
        #pragma unroll
        for (int seg = 0; seg < 6; ++seg) acc += s_scr[seg * 128 + tid];
        g_coeffs[b * 128 + tid] = acc;
    }
}

// ---------------------------------------------------------------------------
// Kernel 2: decoder with f32x2 FMAs. Block = (tile of 64 ty, b), 256 threads.
// ---------------------------------------------------------------------------
__global__ __launch_bounds__(256) void decoder_kernel(
    const float* __restrict__ y_ts, const float* __restrict__ w1,
    const float* __restrict__ b1,   const float* __restrict__ w2,
    const float* __restrict__ b2,   float* __restrict__ out)
{
    __shared__ float sA[128], sB[128], sy[64], sc0[64], sc1[64];
    __shared__ __align__(16) float sw2[64 * 96];
    __shared__ float sh1[64][65];

    int b = blockIdx.y, tile = blockIdx.x;
    int tid = threadIdx.x;

    if (tid < 64) {
        sc0[tid] = g_coeffs[b * 128 + tid];
        sc1[tid] = g_coeffs[b * 128 + 64 + tid];
    } else if (tid < 128) {
        sy[tid - 64] = y_ts[b * TYk + tile * 64 + (tid - 64)];
    }
    __syncthreads();
    if (tid < 128) {
        float a = b1[tid], bb = 0.f;
        #pragma unroll 8
        for (int l = 0; l < 64; ++l) {
            float w = w1[l * 128 + tid];
            a = fmaf(sc0[l], w, a);
            bb = fmaf(sc1[l], w, bb);
        }
        sA[tid] = a; sB[tid] = bb;
    }
    __syncthreads();

    int tg = tid >> 4, jg = tid & 15;
    int ty0 = tg * 4, j0 = jg * 6;
    u64 acc2[4][3];
    #pragma unroll
    for (int r = 0; r < 4; ++r)
        #pragma unroll
        for (int u = 0; u < 3; ++u) acc2[r][u] = 0ull;

    for (int c = 0; c < 2; ++c) {
        for (int i = tid; i < 64 * 96; i += 256) sw2[i] = w2[c * 64 * 96 + i];
        for (int i = tid; i < 64 * 64; i += 256) {
            int ty = i >> 6, ic = i & 63;
            sh1[ty][ic] = fmaxf(fmaf(sy[ty], sB[c * 64 + ic], sA[c * 64 + ic]), 0.f);
        }
        __syncthreads();
        #pragma unroll 4
        for (int ic = 0; ic < 64; ++ic) {
            u64 hd0 = pack2(sh1[ty0][ic],     sh1[ty0][ic]);
            u64 hd1 = pack2(sh1[ty0 + 1][ic], sh1[ty0 + 1][ic]);
            u64 hd2 = pack2(sh1[ty0 + 2][ic], sh1[ty0 + 2][ic]);
            u64 hd3 = pack2(sh1[ty0 + 3][ic], sh1[ty0 + 3][ic]);
            const float* wrow = &sw2[ic * 96 + j0];
            u64 w01 = *(const u64*)&wrow[0];
            u64 w23 = *(const u64*)&wrow[2];
            u64 w45 = *(const u64*)&wrow[4];
            acc2[0][0] = ffma2(hd0, w01, acc2[0][0]);
            acc2[0][1] = ffma2(hd0, w23, acc2[0][1]);
            acc2[0][2] = ffma2(hd0, w45, acc2[0][2]);
            acc2[1][0] = ffma2(hd1, w01, acc2[1][0]);
            acc2[1][1] = ffma2(hd1, w23, acc2[1][1]);
            acc2[1][2] = ffma2(hd1, w45, acc2[1][2]);
            acc2[2][0] = ffma2(hd2, w01, acc2[2][0]);
            acc2[2][1] = ffma2(hd2, w23, acc2[2][1]);
            acc2[2][2] = ffma2(hd2, w45, acc2[2][2]);
            acc2[3][0] = ffma2(hd3, w01, acc2[3][0]);
            acc2[3][1] = ffma2(hd3, w23, acc2[3][1]);
            acc2[3][2] = ffma2(hd3, w45, acc2[3][2]);
        }
        __syncthreads();
    }
    #pragma unroll
    for (int r = 0; r < 4; ++r) {
        int ty = tile * 64 + ty0 + r;
        float* o = out + ((size_t)b * TYk + ty) * Dd + j0;
        #pragma unroll
        for (int u = 0; u < 3; ++u) {
            float2 v = unpack2(acc2[r][u]);
            o[2 * u]     = v.x + b2[j0 + 2 * u];
            o[2 * u + 1] = v.y + b2[j0 + 2 * u + 1];
        }
    }
}

// ---------------------------------------------------------------------------
extern "C" void kernel_launch(void* const* d_in, const int* in_sizes, int n_in,
                              void* d_out, int out_size)
{
    const float* timesteps = (const float*)d_in[0];
    const float* X         = (const float*)d_in[1];
    const float* Mm        = (const float*)d_in[2];
    const float* y_ts      = (const float*)d_in[3];
    const float* te_w      = (const float*)d_in[4];
    const float* te_b      = (const float*)d_in[5];
    const float* query     = (const float*)d_in[6];
    const float* q_w       = (const float*)d_in[7];
    const float* q_b       = (const float*)d_in[8];
    const float* k_w       = (const float*)d_in[9];
    const float* k_b       = (const float*)d_in[10];
    const float* ow        = (const float*)d_in[11];
    const float* ob        = (const float*)d_in[12];
    const float* w1        = (const float*)d_in[13];
    const float* b1        = (const float*)d_in[14];
    const float* w2        = (const float*)d_in[15];
    const float* b2        = (const float*)d_in[16];
    float* out = (float*)d_out;

    precompute_kernel<<<2, 512>>>(query, q_w, q_b, k_w, k_b, ow, ob);
    attn_kernel<<<64, 768>>>(timesteps, X, Mm, te_w, te_b, ow);
    decoder_kernel<<<dim3(8, 64), 256>>>(y_ts, w1, b1, w2, b2, out);
}

// round 3
// speedup vs baseline: 2.6127x; 1.1488x over previous
#include <cuda_runtime.h>
#include <math.h>

#define Bk   64
#define Tk   512
#define Dd   96
#define TYk  512
#define Ek   128
#define Pk   2
#define Lk   64
#define HIDk 128

typedef unsigned long long u64;

// ---------------- f32x2 packed math helpers (sm_103a) ----------------------
__device__ __forceinline__ u64 ffma2(u64 a, u64 b, u64 c) {
    u64 d;
    asm("fma.rn.f32x2 %0, %1, %2, %3;" : "=l"(d) : "l"(a), "l"(b), "l"(c));
    return d;
}
__device__ __forceinline__ u64 pack2(float lo, float hi) {
    u64 d; asm("mov.b64 %0, {%1, %2};" : "=l"(d) : "f"(lo), "f"(hi)); return d;
}
__device__ __forceinline__ float2 unpack2(u64 v) {
    float2 r; asm("mov.b64 {%0, %1}, %2;" : "=f"(r.x), "=f"(r.y) : "l"(v)); return r;
}

// Scratch -------------------------------------------------------------------
__device__ float g_coeffs[64 * 2 * 64];

// ---------------------------------------------------------------------------
// Kernel 1: per-batch attention with integrated precompute. 64 blocks x 768.
// ---------------------------------------------------------------------------
__global__ __launch_bounds__(768) void attn_kernel(
    const float* __restrict__ timesteps, const float* __restrict__ X,
    const float* __restrict__ Mm,        const float* __restrict__ te_w,
    const float* __restrict__ te_b,      const float* __restrict__ ow,
    const float* __restrict__ query,     const float* __restrict__ q_w,
    const float* __restrict__ q_b,       const float* __restrict__ k_w,
    const float* __restrict__ k_b,       const float* __restrict__ ob)
{
    __shared__ __align__(16) float s_vt[128][8];   // folded q.k_w transposed [e'][hp]
    __shared__ __align__(16) float s_et[512][8];   // scores -> exp, [t][hp]
    __shared__ __align__(16) float s_buf[4][768];  // scratch / reduction buffer
    __shared__ float s_xa[8 * 96];
    __shared__ float s_cl[12][64];                 // constL partials
    __shared__ float s_max[8];
    __shared__ float s_c[8];

    int b = blockIdx.x;
    int tid = threadIdx.x;

    // ================= Phase P: per-block precompute =======================
    float* s_q  = &s_buf[0][0];     // 256
    float* s_qp = &s_buf[0][256];   // 256
    if (tid < 256) s_q[tid] = query[tid];
    // constL partials (independent of s_q; do before sync)
    {
        int rg = tid >> 6;          // 0..11
        int l = tid & 63;
        float a = 0.f;
        for (int r = rg; r < 384; r += 12) {
            int h = r / 96, j = r - h * 96;
            a += ow[(h * 192 + 96 + j) * 64 + l];
        }
        s_cl[rg][l] = a;
    }
    __syncthreads();
    if (tid < 256) {                // q_proj = query @ q_w + q_b
        int p = tid >> 7, e = tid & 127;
        float acc = q_b[e];
        #pragma unroll 8
        for (int i = 0; i < 128; ++i)
            acc = fmaf(s_q[p * 128 + i], q_w[i * 128 + e], acc);
        s_qp[tid] = acc;
    }
    __syncthreads();
    // g_v[hp][e'] -> s_vt[e'][hp], g_c -> s_c
    for (int idx = tid; idx < 1024; idx += 768) {
        int hp = idx >> 7, ein = idx & 127;
        int h = hp >> 1, p = hp & 1;
        const float4* kr = (const float4*)(k_w + ein * 128 + h * 32);
        const float*  qp = &s_qp[p * 128 + h * 32];
        float acc = 0.f;
        #pragma unroll
        for (int d4 = 0; d4 < 8; ++d4) {
            float4 kv = __ldg(&kr[d4]);
            acc += qp[d4 * 4] * kv.x + qp[d4 * 4 + 1] * kv.y
                 + qp[d4 * 4 + 2] * kv.z + qp[d4 * 4 + 3] * kv.w;
        }
        s_vt[ein][hp] = acc;
    }
    if (tid < 8) {
        int h = tid >> 1, p = tid & 1;
        float acc = 0.f;
        #pragma unroll
        for (int d = 0; d < 32; ++d)
            acc = fmaf(s_qp[p * 128 + h * 32 + d], k_b[h * 32 + d], acc);
        s_c[tid] = acc;
    }
    __syncthreads();

    // ================= Phase A: scores (transposed store) ==================
    if (tid < 512) {
        float ts = timesteps[b * Tk + tid];
        u64 acc2[4];
        #pragma unroll
        for (int q = 0; q < 4; ++q) acc2[q] = pack2(s_c[2 * q], s_c[2 * q + 1]);
        const float4* w4p = (const float4*)te_w;
        const float4* b4p = (const float4*)te_b;
        #pragma unroll 4
        for (int e4 = 0; e4 < 32; ++e4) {
            float4 w4 = __ldg(&w4p[e4]);
            float4 b4 = __ldg(&b4p[e4]);
            float em[4];
            em[0] = __sinf(fmaf(ts, w4.x, b4.x));   // (e % 4 == 0) -> sin
            em[1] = fmaf(ts, w4.y, b4.y);
            em[2] = fmaf(ts, w4.z, b4.z);
            em[3] = fmaf(ts, w4.w, b4.w);
            #pragma unroll
            for (int j = 0; j < 4; ++j) {
                u64 emd = pack2(em[j], em[j]);
                ulonglong2 va = *(const ulonglong2*)&s_vt[e4 * 4 + j][0];
                ulonglong2 vb = *(const ulonglong2*)&s_vt[e4 * 4 + j][4];
                acc2[0] = ffma2(emd, va.x, acc2[0]);
                acc2[1] = ffma2(emd, va.y, acc2[1]);
                acc2[2] = ffma2(emd, vb.x, acc2[2]);
                acc2[3] = ffma2(emd, vb.y, acc2[3]);
            }
        }
        const float scale = 0.17677669529663687f;  // 1/sqrt(32)
        float2 a0 = unpack2(acc2[0]), a1 = unpack2(acc2[1]);
        float2 a2 = unpack2(acc2[2]), a3 = unpack2(acc2[3]);
        *(float4*)&s_et[tid][0] = make_float4(a0.x * scale, a0.y * scale, a1.x * scale, a1.y * scale);
        *(float4*)&s_et[tid][4] = make_float4(a2.x * scale, a2.y * scale, a3.x * scale, a3.y * scale);
    }
    __syncthreads();

    // ================= Phase B: per-hp max, exp in place ===================
    int warp = tid >> 5, lane = tid & 31;
    if (warp < 8) {
        float m = -1e30f;
        for (int t = lane; t < 512; t += 32) m = fmaxf(m, s_et[t][warp]);
        #pragma unroll
        for (int o = 16; o; o >>= 1) m = fmaxf(m, __shfl_xor_sync(0xffffffffu, m, o));
        if (lane == 0) s_max[warp] = m;
    }
    __syncthreads();
    for (int idx = tid; idx < 8 * 512; idx += 768) {
        int t = idx >> 3, hp = idx & 7;
        s_et[t][hp] = __expf(s_et[t][hp] - s_max[hp]);
    }
    __syncthreads();

    // ================= Phase C: direct-LDG masked accumulation =============
    // thread = (tsub 0..15, f2 0..47); owns f = {2f2, 2f2+1}, t = q*16+tsub
    int tsub = tid / 48, f2 = tid - tsub * 48;
    u64 num[2][4], den[2][4];
    #pragma unroll
    for (int fs = 0; fs < 2; ++fs)
        #pragma unroll
        for (int q = 0; q < 4; ++q) { num[fs][q] = 0ull; den[fs][q] = 0ull; }
    {
        const float2* X2 = (const float2*)(X + (size_t)b * Tk * Dd);
        const float2* M2 = (const float2*)(Mm + (size_t)b * Tk * Dd);
        #pragma unroll 4
        for (int q = 0; q < 32; ++q) {
            int t = q * 16 + tsub;
            float2 x2 = __ldg(&X2[t * 48 + f2]);
            float2 m2 = __ldg(&M2[t * 48 + f2]);
            ulonglong2 e01 = *(const ulonglong2*)&s_et[t][0];
            ulonglong2 e23 = *(const ulonglong2*)&s_et[t][4];
            u64 m0  = pack2(m2.x, m2.x);
            u64 m1  = pack2(m2.y, m2.y);
            float xma = m2.x * x2.x, xmb = m2.y * x2.y;
            u64 xm0 = pack2(xma, xma);
            u64 xm1 = pack2(xmb, xmb);
            den[0][0] = ffma2(e01.x, m0, den[0][0]);
            den[0][1] = ffma2(e01.y, m0, den[0][1]);
            den[0][2] = ffma2(e23.x, m0, den[0][2]);
            den[0][3] = ffma2(e23.y, m0, den[0][3]);
            num[0][0] = ffma2(e01.x, xm0, num[0][0]);
            num[0][1] = ffma2(e01.y, xm0, num[0][1]);
            num[0][2] = ffma2(e23.x, xm0, num[0][2]);
            num[0][3] = ffma2(e23.y, xm0, num[0][3]);
            den[1][0] = ffma2(e01.x, m1, den[1][0]);
            den[1][1] = ffma2(e01.y, m1, den[1][1]);
            den[1][2] = ffma2(e23.x, m1, den[1][2]);
            den[1][3] = ffma2(e23.y, m1, den[1][3]);
            num[1][0] = ffma2(e01.x, xm1, num[1][0]);
            num[1][1] = ffma2(e01.y, xm1, num[1][1]);
            num[1][2] = ffma2(e23.x, xm1, num[1][2]);
            num[1][3] = ffma2(e23.y, xm1, num[1][3]);
        }
    }
    __syncthreads();   // s_buf free from here (phase P scratch done)

    // cross-tsub reduction: 4 tsub-groups per round; num then den
    float r_num = 0.f, r_den = 0.f;   // for (hpr, fr) = (tid/96, tid%96)
    #pragma unroll
    for (int pass = 0; pass < 2; ++pass) {
        #pragma unroll
        for (int g = 0; g < 4; ++g) {
            if ((tsub >> 2) == g) {
                int gl = tsub & 3;
                #pragma unroll
                for (int fs = 0; fs < 2; ++fs) {
                    int f = 2 * f2 + fs;
                    #pragma unroll
                    for (int qq = 0; qq < 4; ++qq) {
                        float2 v = unpack2(pass == 0 ? num[fs][qq] : den[fs][qq]);
                        s_buf[gl][(2 * qq) * 96 + f]     = v.x;
                        s_buf[gl][(2 * qq + 1) * 96 + f] = v.y;
                    }
                }
            }
            __syncthreads();
            float s = s_buf[0][tid] + s_buf[1][tid] + s_buf[2][tid] + s_buf[3][tid];
            if (pass == 0) r_num += s; else r_den += s;
            __syncthreads();
        }
    }
    s_xa[tid] = r_num / r_den;   // tid == hpr*96+fr layout
    __syncthreads();

    // ================= Phase D: coeffs =====================================
    float* s_scr = (float*)s_et;
    {
        int outIdx = tid & 127;   // p*64 + l
        int seg = tid >> 7;       // 0..5
        int p = outIdx >> 6, l = outIdx & 63;
        float acc = 0.f;
        #pragma unroll 4
        for (int r = seg * 64; r < seg * 64 + 64; ++r) {
            int h = r / 96, ff = r - h * 96;
            acc = fmaf(s_xa[(h * 2 + p) * 96 + ff], ow[(h * 192 + ff) * 64 + l], acc);
        }
        s_scr[tid] = acc;
    }
    __syncthreads();
    if (tid < 128) {
        int l = tid & 63;
        float acc = ob[l];
        #pragma unroll
        for (int g = 0; g < 12; ++g) acc += s_cl[g][l];
        #pragma unroll
        for (int seg = 0; seg < 6; ++seg) acc += s_scr[seg * 128 + tid];
        g_coeffs[b * 128 + tid] = acc;
    }
}

// ---------------------------------------------------------------------------
// Kernel 2: decoder with f32x2 FMAs. Block = (tile of 64 ty, b), 256 threads.
// ---------------------------------------------------------------------------
__global__ __launch_bounds__(256) void decoder_kernel(
    const float* __restrict__ y_ts, const float* __restrict__ w1,
    const float* __restrict__ b1,   const float* __restrict__ w2,
    const float* __restrict__ b2,   float* __restrict__ out)
{
    __shared__ float sA[128], sB[128], sy[64], sc0[64], sc1[64];
    __shared__ __align__(16) float sw2[64 * 96];
    __shared__ float sh1[64][65];

    int b = blockIdx.y, tile = blockIdx.x;
    int tid = threadIdx.x;

    if (tid < 64) {
        sc0[tid] = g_coeffs[b * 128 + tid];
        sc1[tid] = g_coeffs[b * 128 + 64 + tid];
    } else if (tid < 128) {
        sy[tid - 64] = y_ts[b * TYk + tile * 64 + (tid - 64)];
    }
    __syncthreads();
    if (tid < 128) {
        float a = b1[tid], bb = 0.f;
        #pragma unroll 8
        for (int l = 0; l < 64; ++l) {
            float w = w1[l * 128 + tid];
            a = fmaf(sc0[l], w, a);
            bb = fmaf(sc1[l], w, bb);
        }
        sA[tid] = a; sB[tid] = bb;
    }
    __syncthreads();

    int tg = tid >> 4, jg = tid & 15;
    int ty0 = tg * 4, j0 = jg * 6;
    u64 acc2[4][3];
    #pragma unroll
    for (int r = 0; r < 4; ++r)
        #pragma unroll
        for (int u = 0; u < 3; ++u) acc2[r][u] = 0ull;

    for (int c = 0; c < 2; ++c) {
        for (int i = tid; i < 64 * 96; i += 256) sw2[i] = w2[c * 64 * 96 + i];
        for (int i = tid; i < 64 * 64; i += 256) {
            int ty = i >> 6, ic = i & 63;
            sh1[ty][ic] = fmaxf(fmaf(sy[ty], sB[c * 64 + ic], sA[c * 64 + ic]), 0.f);
        }
        __syncthreads();
        #pragma unroll 4
        for (int ic = 0; ic < 64; ++ic) {
            u64 hd0 = pack2(sh1[ty0][ic],     sh1[ty0][ic]);
            u64 hd1 = pack2(sh1[ty0 + 1][ic], sh1[ty0 + 1][ic]);
            u64 hd2 = pack2(sh1[ty0 + 2][ic], sh1[ty0 + 2][ic]);
            u64 hd3 = pack2(sh1[ty0 + 3][ic], sh1[ty0 + 3][ic]);
            const float* wrow = &sw2[ic * 96 + j0];
            u64 w01 = *(const u64*)&wrow[0];
            u64 w23 = *(const u64*)&wrow[2];
            u64 w45 = *(const u64*)&wrow[4];
            acc2[0][0] = ffma2(hd0, w01, acc2[0][0]);
            acc2[0][1] = ffma2(hd0, w23, acc2[0][1]);
            acc2[0][2] = ffma2(hd0, w45, acc2[0][2]);
            acc2[1][0] = ffma2(hd1, w01, acc2[1][0]);
            acc2[1][1] = ffma2(hd1, w23, acc2[1][1]);
            acc2[1][2] = ffma2(hd1, w45, acc2[1][2]);
            acc2[2][0] = ffma2(hd2, w01, acc2[2][0]);
            acc2[2][1] = ffma2(hd2, w23, acc2[2][1]);
            acc2[2][2] = ffma2(hd2, w45, acc2[2][2]);
            acc2[3][0] = ffma2(hd3, w01, acc2[3][0]);
            acc2[3][1] = ffma2(hd3, w23, acc2[3][1]);
            acc2[3][2] = ffma2(hd3, w45, acc2[3][2]);
        }
        __syncthreads();
    }
    #pragma unroll
    for (int r = 0; r < 4; ++r) {
        int ty = tile * 64 + ty0 + r;
        float* o = out + ((size_t)b * TYk + ty) * Dd + j0;
        #pragma unroll
        for (int u = 0; u < 3; ++u) {
            float2 v = unpack2(acc2[r][u]);
            o[2 * u]     = v.x + b2[j0 + 2 * u];
            o[2 * u + 1] = v.y + b2[j0 + 2 * u + 1];
        }
    }
}

// ---------------------------------------------------------------------------
extern "C" void kernel_launch(void* const* d_in, const int* in_sizes, int n_in,
                              void* d_out, int out_size)
{
    const float* timesteps = (const float*)d_in[0];
    const float* X         = (const float*)d_in[1];
    const float* Mm        = (const float*)d_in[2];
    const float* y_ts      = (const float*)d_in[3];
    const float* te_w      = (const float*)d_in[4];
    const float* te_b      = (const float*)d_in[5];
    const float* query     = (const float*)d_in[6];
    const float* q_w       = (const float*)d_in[7];
    const float* q_b       = (const float*)d_in[8];
    const float* k_w       = (const float*)d_in[9];
    const float* k_b       = (const float*)d_in[10];
    const float* ow        = (const float*)d_in[11];
    const float* ob        = (const float*)d_in[12];
    const float* w1        = (const float*)d_in[13];
    const float* b1        = (const float*)d_in[14];
    const float* w2        = (const float*)d_in[15];
    const float* b2        = (const float*)d_in[16];
    float* out = (float*)d_out;

    attn_kernel<<<64, 768>>>(timesteps, X, Mm, te_w, te_b, ow,
                             query, q_w, q_b, k_w, k_b, ob);
    decoder_kernel<<<dim3(8, 64), 256>>>(y_ts, w1, b1, w2, b2, out);
}

// round 4
// speedup vs baseline: 2.7222x; 1.0419x over previous
#include <cuda_runtime.h>
#include <math.h>

#define Bk   64
#define Tk   512
#define Dd   96
#define TYk  512
#define Ek   128
#define Pk   2
#define Lk   64
#define HIDk 128

typedef unsigned long long u64;

// ---------------- f32x2 packed math helpers (sm_103a) ----------------------
__device__ __forceinline__ u64 ffma2(u64 a, u64 b, u64 c) {
    u64 d;
    asm("fma.rn.f32x2 %0, %1, %2, %3;" : "=l"(d) : "l"(a), "l"(b), "l"(c));
    return d;
}
__device__ __forceinline__ u64 pack2(float lo, float hi) {
    u64 d; asm("mov.b64 %0, {%1, %2};" : "=l"(d) : "f"(lo), "f"(hi)); return d;
}
__device__ __forceinline__ float2 unpack2(u64 v) {
    float2 r; asm("mov.b64 {%0, %1}, %2;" : "=f"(r.x), "=f"(r.y) : "l"(v)); return r;
}

// Scratch -------------------------------------------------------------------
__device__ float g_coeffs[2][64 * 128];   // per feature-half partial coeffs

// ---------------------------------------------------------------------------
// Kernel 1: attention, feature-split. grid = (2 f-halves, 64 b) x 768 thr.
// ---------------------------------------------------------------------------
__global__ __launch_bounds__(768) void attn_kernel(
    const float* __restrict__ timesteps, const float* __restrict__ X,
    const float* __restrict__ Mm,        const float* __restrict__ te_w,
    const float* __restrict__ te_b,      const float* __restrict__ ow,
    const float* __restrict__ query,     const float* __restrict__ q_w,
    const float* __restrict__ q_b,       const float* __restrict__ k_w,
    const float* __restrict__ k_b,       const float* __restrict__ ob)
{
    __shared__ __align__(16) float s_vt[128][8];   // folded q.k_w transposed [e'][hp]
    __shared__ __align__(16) float s_et[512][8];   // scores -> exp, [t][hp]
    __shared__ __align__(16) float s_buf[4][768];  // scratch / reduction buffer
    __shared__ float s_xa[8 * 48];                 // this half's weighted means
    __shared__ float s_den[8 * 48];
    __shared__ float s_cl[12][64];                 // constL partials (this half)
    __shared__ float s_max[8];
    __shared__ float s_c[8];

    int fh = blockIdx.x;        // feature half 0/1 (features fh*48 .. +48)
    int b  = blockIdx.y;
    int tid = threadIdx.x;

    // ================= Phase P: per-block precompute =======================
    float* s_q  = &s_buf[0][0];     // 256
    float* s_qp = &s_buf[0][256];   // 256
    if (tid < 256) s_q[tid] = query[tid];
    // constL partials: this half's 192 "ones" rows (h x 48 j)
    {
        int rg = tid >> 6;          // 0..11
        int l = tid & 63;
        float a = 0.f;
        #pragma unroll 4
        for (int r = rg; r < 192; r += 12) {
            int h = r / 48, jj = r - h * 48;
            a += ow[(h * 192 + 96 + fh * 48 + jj) * 64 + l];
        }
        s_cl[rg][l] = a;
    }
    __syncthreads();
    if (tid < 256) {                // q_proj = query @ q_w + q_b
        int p = tid >> 7, e = tid & 127;
        float acc = q_b[e];
        #pragma unroll 8
        for (int i = 0; i < 128; ++i)
            acc = fmaf(s_q[p * 128 + i], q_w[i * 128 + e], acc);
        s_qp[tid] = acc;
    }
    __syncthreads();
    for (int idx = tid; idx < 1024; idx += 768) {
        int hp = idx >> 7, ein = idx & 127;
        int h = hp >> 1, p = hp & 1;
        const float4* kr = (const float4*)(k_w + ein * 128 + h * 32);
        const float*  qp = &s_qp[p * 128 + h * 32];
        float acc = 0.f;
        #pragma unroll
        for (int d4 = 0; d4 < 8; ++d4) {
            float4 kv = __ldg(&kr[d4]);
            acc += qp[d4 * 4] * kv.x + qp[d4 * 4 + 1] * kv.y
                 + qp[d4 * 4 + 2] * kv.z + qp[d4 * 4 + 3] * kv.w;
        }
        s_vt[ein][hp] = acc;
    }
    if (tid < 8) {
        int h = tid >> 1, p = tid & 1;
        float acc = 0.f;
        #pragma unroll
        for (int d = 0; d < 32; ++d)
            acc = fmaf(s_qp[p * 128 + h * 32 + d], k_b[h * 32 + d], acc);
        s_c[tid] = acc;
    }
    __syncthreads();

    // ================= Phase A: scores (duplicated per half) ===============
    if (tid < 512) {
        float ts = timesteps[b * Tk + tid];
        u64 acc2[4];
        #pragma unroll
        for (int q = 0; q < 4; ++q) acc2[q] = pack2(s_c[2 * q], s_c[2 * q + 1]);
        const float4* w4p = (const float4*)te_w;
        const float4* b4p = (const float4*)te_b;
        #pragma unroll 4
        for (int e4 = 0; e4 < 32; ++e4) {
            float4 w4 = __ldg(&w4p[e4]);
            float4 b4 = __ldg(&b4p[e4]);
            float em[4];
            em[0] = __sinf(fmaf(ts, w4.x, b4.x));   // (e % 4 == 0) -> sin
            em[1] = fmaf(ts, w4.y, b4.y);
            em[2] = fmaf(ts, w4.z, b4.z);
            em[3] = fmaf(ts, w4.w, b4.w);
            #pragma unroll
            for (int j = 0; j < 4; ++j) {
                u64 emd = pack2(em[j], em[j]);
                ulonglong2 va = *(const ulonglong2*)&s_vt[e4 * 4 + j][0];
                ulonglong2 vb = *(const ulonglong2*)&s_vt[e4 * 4 + j][4];
                acc2[0] = ffma2(emd, va.x, acc2[0]);
                acc2[1] = ffma2(emd, va.y, acc2[1]);
                acc2[2] = ffma2(emd, vb.x, acc2[2]);
                acc2[3] = ffma2(emd, vb.y, acc2[3]);
            }
        }
        const float scale = 0.17677669529663687f;  // 1/sqrt(32)
        float2 a0 = unpack2(acc2[0]), a1 = unpack2(acc2[1]);
        float2 a2 = unpack2(acc2[2]), a3 = unpack2(acc2[3]);
        *(float4*)&s_et[tid][0] = make_float4(a0.x * scale, a0.y * scale, a1.x * scale, a1.y * scale);
        *(float4*)&s_et[tid][4] = make_float4(a2.x * scale, a2.y * scale, a3.x * scale, a3.y * scale);
    }
    __syncthreads();

    // ================= Phase B: per-hp max, exp in place ===================
    int warp = tid >> 5, lane = tid & 31;
    if (warp < 8) {
        float m = -1e30f;
        for (int t = lane; t < 512; t += 32) m = fmaxf(m, s_et[t][warp]);
        #pragma unroll
        for (int o = 16; o; o >>= 1) m = fmaxf(m, __shfl_xor_sync(0xffffffffu, m, o));
        if (lane == 0) s_max[warp] = m;
    }
    __syncthreads();
    for (int idx = tid; idx < 8 * 512; idx += 768) {
        int t = idx >> 3, hp = idx & 7;
        s_et[t][hp] = __expf(s_et[t][hp] - s_max[hp]);
    }
    __syncthreads();

    // ================= Phase C: direct-LDG masked accumulation =============
    // thread = (tsub 0..31, f2l 0..23); f pair = fh*48 + 2*f2l(+1); t = q*32+tsub
    int tsub = tid / 24, f2l = tid - tsub * 24;
    u64 num[2][4], den[2][4];
    #pragma unroll
    for (int fs = 0; fs < 2; ++fs)
        #pragma unroll
        for (int q = 0; q < 4; ++q) { num[fs][q] = 0ull; den[fs][q] = 0ull; }
    {
        const float2* X2 = (const float2*)(X + (size_t)b * Tk * Dd);
        const float2* M2 = (const float2*)(Mm + (size_t)b * Tk * Dd);
        int fb = fh * 24;
        #pragma unroll 4
        for (int q = 0; q < 16; ++q) {
            int t = q * 32 + tsub;
            float2 x2 = __ldg(&X2[t * 48 + fb + f2l]);
            float2 m2 = __ldg(&M2[t * 48 + fb + f2l]);
            ulonglong2 e01 = *(const ulonglong2*)&s_et[t][0];
            ulonglong2 e23 = *(const ulonglong2*)&s_et[t][4];
            u64 m0  = pack2(m2.x, m2.x);
            u64 m1  = pack2(m2.y, m2.y);
            float xma = m2.x * x2.x, xmb = m2.y * x2.y;
            u64 xm0 = pack2(xma, xma);
            u64 xm1 = pack2(xmb, xmb);
            den[0][0] = ffma2(e01.x, m0, den[0][0]);
            den[0][1] = ffma2(e01.y, m0, den[0][1]);
            den[0][2] = ffma2(e23.x, m0, den[0][2]);
            den[0][3] = ffma2(e23.y, m0, den[0][3]);
            num[0][0] = ffma2(e01.x, xm0, num[0][0]);
            num[0][1] = ffma2(e01.y, xm0, num[0][1]);
            num[0][2] = ffma2(e23.x, xm0, num[0][2]);
            num[0][3] = ffma2(e23.y, xm0, num[0][3]);
            den[1][0] = ffma2(e01.x, m1, den[1][0]);
            den[1][1] = ffma2(e01.y, m1, den[1][1]);
            den[1][2] = ffma2(e23.x, m1, den[1][2]);
            den[1][3] = ffma2(e23.y, m1, den[1][3]);
            num[1][0] = ffma2(e01.x, xm1, num[1][0]);
            num[1][1] = ffma2(e01.y, xm1, num[1][1]);
            num[1][2] = ffma2(e23.x, xm1, num[1][2]);
            num[1][3] = ffma2(e23.y, xm1, num[1][3]);
        }
    }
    __syncthreads();   // phase-P scratch in s_buf fully retired

    // cross-tsub reduction: 8 rounds x 4 tsub-groups; slot = tid
    //   tid <  384 : num slot (hp = tid/48, fl = tid%48)
    //   tid >= 384 : den slot
    float r_acc = 0.f;
    #pragma unroll
    for (int g = 0; g < 8; ++g) {
        if ((tsub >> 2) == g) {
            int gl = tsub & 3;
            #pragma unroll
            for (int fs = 0; fs < 2; ++fs) {
                int fl = 2 * f2l + fs;
                #pragma unroll
                for (int qq = 0; qq < 4; ++qq) {
                    float2 vn = unpack2(num[fs][qq]);
                    s_buf[gl][(2 * qq) * 48 + fl]           = vn.x;
                    s_buf[gl][(2 * qq + 1) * 48 + fl]       = vn.y;
                    float2 vd = unpack2(den[fs][qq]);
                    s_buf[gl][384 + (2 * qq) * 48 + fl]     = vd.x;
                    s_buf[gl][384 + (2 * qq + 1) * 48 + fl] = vd.y;
                }
            }
        }
        __syncthreads();
        r_acc += s_buf[0][tid] + s_buf[1][tid] + s_buf[2][tid] + s_buf[3][tid];
        __syncthreads();
    }
    if (tid >= 384) s_den[tid - 384] = r_acc;
    __syncthreads();
    if (tid < 384) s_xa[tid] = r_acc / s_den[tid];
    __syncthreads();

    // ================= Phase D: partial coeffs (this half's 192 rows) ======
    float* s_scr = (float*)s_et;
    {
        int outIdx = tid & 127;   // p*64 + l
        int seg = tid >> 7;       // 0..5, rows seg*32 .. +32
        int p = outIdx >> 6, l = outIdx & 63;
        float acc = 0.f;
        #pragma unroll 4
        for (int r = seg * 32; r < seg * 32 + 32; ++r) {
            int h = r / 48, fl = r - h * 48;
            acc = fmaf(s_xa[(h * 2 + p) * 48 + fl],
                       ow[(h * 192 + fh * 48 + fl) * 64 + l], acc);
        }
        s_scr[tid] = acc;
    }
    __syncthreads();
    if (tid < 128) {
        int l = tid & 63;
        float acc = (fh == 0) ? ob[l] : 0.f;
        #pragma unroll
        for (int g = 0; g < 12; ++g) acc += s_cl[g][l];
        #pragma unroll
        for (int seg = 0; seg < 6; ++seg) acc += s_scr[seg * 128 + tid];
        g_coeffs[fh][b * 128 + tid] = acc;
    }
}

// ---------------------------------------------------------------------------
// Kernel 2: decoder. Block = (tile of 64 ty, b), 128 threads.
//   thread = (tg 0..7 -> 8 ty, jg 0..15 -> 6 j). h recomputed in registers.
// ---------------------------------------------------------------------------
__global__ __launch_bounds__(128) void decoder_kernel(
    const float* __restrict__ y_ts, const float* __restrict__ w1,
    const float* __restrict__ b1,   const float* __restrict__ w2,
    const float* __restrict__ b2,   float* __restrict__ out)
{
    __shared__ float sA[128], sB[128], sy[64], sc0[64], sc1[64];
    __shared__ __align__(16) float sw2[64 * 96];

    int b = blockIdx.y, tile = blockIdx.x;
    int tid = threadIdx.x;

    if (tid < 64) {
        sc0[tid] = g_coeffs[0][b * 128 + tid] + g_coeffs[1][b * 128 + tid];
        sy[tid]  = y_ts[b * TYk + tile * 64 + tid];
    } else {
        int l = tid - 64;
        sc1[l] = g_coeffs[0][b * 128 + 64 + l] + g_coeffs[1][b * 128 + 64 + l];
    }
    __syncthreads();
    {
        float a = b1[tid], bb = 0.f;
        #pragma unroll 8
        for (int l = 0; l < 64; ++l) {
            float w = w1[l * 128 + tid];
            a = fmaf(sc0[l], w, a);
            bb = fmaf(sc1[l], w, bb);
        }
        sA[tid] = a; sB[tid] = bb;
    }
    __syncthreads();

    int tg = tid >> 4, jg = tid & 15;
    int ty0 = tg * 8, j0 = jg * 6;
    u64 yp[4];
    #pragma unroll
    for (int r = 0; r < 4; ++r) yp[r] = pack2(sy[ty0 + 2 * r], sy[ty0 + 2 * r + 1]);

    u64 acc2[8][3];
    #pragma unroll
    for (int r = 0; r < 8; ++r)
        #pragma unroll
        for (int u = 0; u < 3; ++u) acc2[r][u] = 0ull;

    for (int c = 0; c < 2; ++c) {
        {   // stage w2 chunk (float4)
            const float4* src = (const float4*)(w2 + c * 64 * 96);
            float4* dst = (float4*)sw2;
            #pragma unroll
            for (int i = tid; i < 64 * 96 / 4; i += 128) dst[i] = src[i];
        }
        __syncthreads();
        #pragma unroll 2
        for (int ic = 0; ic < 64; ++ic) {
            float a  = sA[c * 64 + ic];
            float bb = sB[c * 64 + ic];
            u64 ad = pack2(a, a), bd = pack2(bb, bb);
            float hv[8];
            #pragma unroll
            for (int r = 0; r < 4; ++r) {
                float2 h2 = unpack2(ffma2(yp[r], bd, ad));
                hv[2 * r]     = fmaxf(h2.x, 0.f);
                hv[2 * r + 1] = fmaxf(h2.y, 0.f);
            }
            const float* wrow = &sw2[ic * 96 + j0];
            u64 w01 = *(const u64*)&wrow[0];
            u64 w23 = *(const u64*)&wrow[2];
            u64 w45 = *(const u64*)&wrow[4];
            #pragma unroll
            for (int r = 0; r < 8; ++r) {
                u64 hd = pack2(hv[r], hv[r]);
                acc2[r][0] = ffma2(hd, w01, acc2[r][0]);
                acc2[r][1] = ffma2(hd, w23, acc2[r][1]);
                acc2[r][2] = ffma2(hd, w45, acc2[r][2]);
            }
        }
        __syncthreads();
    }

    float b2v[6];
    #pragma unroll
    for (int u = 0; u < 6; ++u) b2v[u] = b2[j0 + u];
    #pragma unroll
    for (int r = 0; r < 8; ++r) {
        int ty = tile * 64 + ty0 + r;
        float* o = out + ((size_t)b * TYk + ty) * Dd + j0;
        #pragma unroll
        for (int u = 0; u < 3; ++u) {
            float2 v = unpack2(acc2[r][u]);
            o[2 * u]     = v.x + b2v[2 * u];
            o[2 * u + 1] = v.y + b2v[2 * u + 1];
        }
    }
}

// ---------------------------------------------------------------------------
extern "C" void kernel_launch(void* const* d_in, const int* in_sizes, int n_in,
                              void* d_out, int out_size)
{
    const float* timesteps = (const float*)d_in[0];
    const float* X         = (const float*)d_in[1];
    const float* Mm        = (const float*)d_in[2];
    const float* y_ts      = (const float*)d_in[3];
    const float* te_w      = (const float*)d_in[4];
    const float* te_b      = (const float*)d_in[5];
    const float* query     = (const float*)d_in[6];
    const float* q_w       = (const float*)d_in[7];
    const float* q_b       = (const float*)d_in[8];
    const float* k_w       = (const float*)d_in[9];
    const float* k_b       = (const float*)d_in[10];
    const float* ow        = (const float*)d_in[11];
    const float* ob        = (const float*)d_in[12];
    const float* w1        = (const float*)d_in[13];
    const float* b1        = (const float*)d_in[14];
    const float* w2        = (const float*)d_in[15];
    const float* b2        = (const float*)d_in[16];
    float* out = (float*)d_out;

    attn_kernel<<<dim3(2, 64), 768>>>(timesteps, X, Mm, te_w, te_b, ow,
                                      query, q_w, q_b, k_w, k_b, ob);
    decoder_kernel<<<dim3(8, 64), 128>>>(y_ts, w1, b1, w2, b2, out);
}